// round 1
// baseline (speedup 1.0000x reference)
#include <cuda_runtime.h>
#include <cuda_bf16.h>

#define BATCH 32
#define NAG   6
#define KS    256
#define QS    256
#define CHW   (512*32*32)       /* 524288 floats per (b,n) slab */
#define V4PB  (CHW/4)           /* 131072 float4 per (b,n) slab */

// Scratch for attention weights (allocation-free rule: __device__ global)
__device__ float g_attn[BATCH * NAG];

// ---------------------------------------------------------------------------
// Kernel 1: query = q@W^T + b ; scores = k . query ; sparsemax over N=6
// One block per batch, 256 threads.
// ---------------------------------------------------------------------------
__global__ void attn_kernel(const float* __restrict__ q,
                            const float* __restrict__ k,
                            const float* __restrict__ W,
                            const float* __restrict__ bias,
                            float* __restrict__ out_attn,
                            int write_attn) {
    const int b = blockIdx.x;
    const int t = threadIdx.x;

    __shared__ float4 sq4[QS / 4];
    __shared__ float  squery[KS];
    __shared__ float  sscore[NAG];

    if (t < QS / 4) sq4[t] = ((const float4*)(q + b * QS))[t];
    __syncthreads();

    // query[t] = bias[t] + sum_d q[b,d] * W[t,d]
    float acc = bias[t];
    const float4* wrow = (const float4*)(W + t * QS);
    #pragma unroll 16
    for (int d = 0; d < QS / 4; d++) {
        float4 wv = wrow[d];
        float4 qv = sq4[d];
        acc = fmaf(wv.x, qv.x, acc);
        acc = fmaf(wv.y, qv.y, acc);
        acc = fmaf(wv.z, qv.z, acc);
        acc = fmaf(wv.w, qv.w, acc);
    }
    squery[t] = acc;
    __syncthreads();

    // 6 warps compute the 6 agent scores
    const int wid = t >> 5, lane = t & 31;
    if (wid < NAG) {
        const float* krow = k + (b * NAG + wid) * KS;
        float s = 0.f;
        #pragma unroll
        for (int d = lane; d < KS; d += 32) s = fmaf(krow[d], squery[d], s);
        #pragma unroll
        for (int o = 16; o; o >>= 1) s += __shfl_xor_sync(0xffffffffu, s, o);
        if (lane == 0) sscore[wid] = s;
    }
    __syncthreads();

    // Sparsemax over 6 values, done serially on thread 0 (trivial cost)
    if (t == 0) {
        float z[NAG], zs[NAG];
        #pragma unroll
        for (int n = 0; n < NAG; n++) { z[n] = sscore[n]; zs[n] = z[n]; }
        // insertion sort descending
        #pragma unroll
        for (int i = 1; i < NAG; i++) {
            float key = zs[i]; int j = i - 1;
            while (j >= 0 && zs[j] < key) { zs[j + 1] = zs[j]; j--; }
            zs[j + 1] = key;
        }
        float cs[NAG], run = 0.f;
        #pragma unroll
        for (int r = 0; r < NAG; r++) { run += zs[r]; cs[r] = run; }
        // k = count of support (matches reference's jnp.sum of booleans)
        int kk = 0;
        #pragma unroll
        for (int r = 1; r <= NAG; r++)
            if (1.0f + (float)r * zs[r - 1] > cs[r - 1]) kk++;
        const float tau = (cs[kk - 1] - 1.0f) / (float)kk;
        #pragma unroll
        for (int n = 0; n < NAG; n++) {
            float p = fmaxf(z[n] - tau, 0.0f);
            g_attn[b * NAG + n] = p;
            if (write_attn) out_attn[b * NAG + n] = p;
        }
    }
}

// ---------------------------------------------------------------------------
// Kernel 2: output[b, :] = sum_n attn[b,n] * v[b,n,:]
// float4, one element per thread; skips zero-weight agents (uniform branch).
// ---------------------------------------------------------------------------
__global__ void __launch_bounds__(256)
wsum_kernel(const float* __restrict__ v, float* __restrict__ out) {
    const int i4 = blockIdx.x * 256 + threadIdx.x;   // [0, 32*131072)
    const int b      = i4 >> 17;                     // 131072 = 2^17
    const int within = i4 & (V4PB - 1);

    __shared__ float sw[NAG];
    if (threadIdx.x < NAG) sw[threadIdx.x] = g_attn[b * NAG + threadIdx.x];
    __syncthreads();

    const float4* vb = (const float4*)v + (size_t)b * NAG * V4PB + within;
    float4 acc = make_float4(0.f, 0.f, 0.f, 0.f);
    #pragma unroll
    for (int n = 0; n < NAG; n++) {
        const float w = sw[n];
        if (w != 0.0f) {               // warp-uniform: whole block shares b
            float4 x = vb[(size_t)n * V4PB];
            acc.x = fmaf(w, x.x, acc.x);
            acc.y = fmaf(w, x.y, acc.y);
            acc.z = fmaf(w, x.z, acc.z);
            acc.w = fmaf(w, x.w, acc.w);
        }
    }
    ((float4*)out)[i4] = acc;
}

// ---------------------------------------------------------------------------
extern "C" void kernel_launch(void* const* d_in, const int* in_sizes, int n_in,
                              void* d_out, int out_size) {
    const float* q    = (const float*)d_in[0];
    const float* k    = (const float*)d_in[1];
    const float* v    = (const float*)d_in[2];
    const float* W    = (const float*)d_in[3];
    const float* bias = (const float*)d_in[4];

    float* out = (float*)d_out;
    const long long out_main = (long long)BATCH * CHW;        // 16777216
    const int write_attn = (out_size >= out_main + BATCH * NAG) ? 1 : 0;
    float* out_attn = out + out_main;

    attn_kernel<<<BATCH, 256>>>(q, k, W, bias, out_attn, write_attn);

    const int n4     = BATCH * V4PB;        // 4194304 float4 outputs
    const int blocks = n4 / 256;            // 16384
    wsum_kernel<<<blocks, 256>>>(v, out);
}

// round 2
// speedup vs baseline: 1.3048x; 1.3048x over previous
#include <cuda_runtime.h>
#include <cuda_bf16.h>

#define BATCH 32
#define NAG   6
#define KS    256
#define QS    256
#define CHW   (512*32*32)       /* 524288 floats per (b,n) slab */
#define V4PB  (CHW/4)           /* 131072 float4 per (b,n) slab */

// Scratch (allocation-free rule: __device__ globals)
__device__ float g_query[BATCH * KS];
__device__ float g_attn[BATCH * NAG];

// ---------------------------------------------------------------------------
// Kernel 1: query[b,kk] = bias[kk] + sum_d W[kk,d] * q[b,d]
// One warp per (b,kk) dot. grid = 32 batches * 32 blocks, 8 warps/block.
// ---------------------------------------------------------------------------
__global__ void __launch_bounds__(256)
query_kernel(const float* __restrict__ q,
             const float* __restrict__ W,
             const float* __restrict__ bias) {
    const int b    = blockIdx.x >> 5;                 // 32 blocks per batch
    const int kk   = ((blockIdx.x & 31) << 3) + (threadIdx.x >> 5);
    const int lane = threadIdx.x & 31;

    const float4* wr = (const float4*)(W + (size_t)kk * QS);   // 64 float4
    const float4* qr = (const float4*)(q + (size_t)b  * QS);

    float4 w0 = wr[lane],      q0 = qr[lane];
    float4 w1 = wr[lane + 32], q1 = qr[lane + 32];

    float s = w0.x * q0.x + w0.y * q0.y + w0.z * q0.z + w0.w * q0.w
            + w1.x * q1.x + w1.y * q1.y + w1.z * q1.z + w1.w * q1.w;
    #pragma unroll
    for (int o = 16; o; o >>= 1) s += __shfl_xor_sync(0xffffffffu, s, o);

    if (lane == 0) g_query[b * KS + kk] = s + bias[kk];
}

// ---------------------------------------------------------------------------
// Kernel 2: scores = k . query ; sparsemax over N=6. One block per batch.
// ---------------------------------------------------------------------------
__global__ void __launch_bounds__(192)
score_kernel(const float* __restrict__ k,
             float* __restrict__ out_attn,
             int write_attn) {
    const int b    = blockIdx.x;
    const int wid  = threadIdx.x >> 5;   // 6 warps = 6 agents
    const int lane = threadIdx.x & 31;

    __shared__ float sscore[NAG];

    {
        const float4* kr = (const float4*)(k + (size_t)(b * NAG + wid) * KS);
        const float4* qr = (const float4*)(g_query + (size_t)b * KS);
        float4 k0 = kr[lane],      q0 = qr[lane];
        float4 k1 = kr[lane + 32], q1 = qr[lane + 32];
        float s = k0.x * q0.x + k0.y * q0.y + k0.z * q0.z + k0.w * q0.w
                + k1.x * q1.x + k1.y * q1.y + k1.z * q1.z + k1.w * q1.w;
        #pragma unroll
        for (int o = 16; o; o >>= 1) s += __shfl_xor_sync(0xffffffffu, s, o);
        if (lane == 0) sscore[wid] = s;
    }
    __syncthreads();

    if (threadIdx.x == 0) {
        float z[NAG], zs[NAG];
        #pragma unroll
        for (int n = 0; n < NAG; n++) { z[n] = sscore[n]; zs[n] = z[n]; }
        #pragma unroll
        for (int i = 1; i < NAG; i++) {           // insertion sort, descending
            float key = zs[i]; int j = i - 1;
            while (j >= 0 && zs[j] < key) { zs[j + 1] = zs[j]; j--; }
            zs[j + 1] = key;
        }
        float cs[NAG], run = 0.f;
        #pragma unroll
        for (int r = 0; r < NAG; r++) { run += zs[r]; cs[r] = run; }
        int kk = 0;
        #pragma unroll
        for (int r = 1; r <= NAG; r++)
            if (1.0f + (float)r * zs[r - 1] > cs[r - 1]) kk++;
        const float tau = (cs[kk - 1] - 1.0f) / (float)kk;
        #pragma unroll
        for (int n = 0; n < NAG; n++) {
            float p = fmaxf(z[n] - tau, 0.0f);
            g_attn[b * NAG + n] = p;
            if (write_attn) out_attn[b * NAG + n] = p;
        }
    }
}

// ---------------------------------------------------------------------------
// Kernel 3: output[b,:] = sum_n attn[b,n] * v[b,n,:]
// 4 float4 per thread (front-batched -> MLP_p1 = 4). Skips zero-weight agents
// (branch is block-uniform: whole block shares one batch).
// grid = 4096 blocks, 256 threads; each block covers 1024 contiguous float4.
// ---------------------------------------------------------------------------
__global__ void __launch_bounds__(256)
wsum_kernel(const float* __restrict__ v, float* __restrict__ out) {
    const int b    = blockIdx.x >> 7;                       // 128 blocks/batch
    const int base = ((blockIdx.x & 127) << 10) + threadIdx.x;  // within slab

    __shared__ float sw[NAG];
    if (threadIdx.x < NAG) sw[threadIdx.x] = g_attn[b * NAG + threadIdx.x];
    __syncthreads();

    const float4* vb = (const float4*)v + (size_t)b * NAG * V4PB + base;

    float4 acc0 = make_float4(0.f, 0.f, 0.f, 0.f);
    float4 acc1 = acc0, acc2 = acc0, acc3 = acc0;

    #pragma unroll
    for (int n = 0; n < NAG; n++) {
        const float w = sw[n];
        if (w != 0.0f) {
            const float4* p = vb + (size_t)n * V4PB;
            float4 x0 = p[0];
            float4 x1 = p[256];
            float4 x2 = p[512];
            float4 x3 = p[768];
            acc0.x = fmaf(w, x0.x, acc0.x); acc0.y = fmaf(w, x0.y, acc0.y);
            acc0.z = fmaf(w, x0.z, acc0.z); acc0.w = fmaf(w, x0.w, acc0.w);
            acc1.x = fmaf(w, x1.x, acc1.x); acc1.y = fmaf(w, x1.y, acc1.y);
            acc1.z = fmaf(w, x1.z, acc1.z); acc1.w = fmaf(w, x1.w, acc1.w);
            acc2.x = fmaf(w, x2.x, acc2.x); acc2.y = fmaf(w, x2.y, acc2.y);
            acc2.z = fmaf(w, x2.z, acc2.z); acc2.w = fmaf(w, x2.w, acc2.w);
            acc3.x = fmaf(w, x3.x, acc3.x); acc3.y = fmaf(w, x3.y, acc3.y);
            acc3.z = fmaf(w, x3.z, acc3.z); acc3.w = fmaf(w, x3.w, acc3.w);
        }
    }

    float4* ob = (float4*)out + (size_t)b * V4PB + base;
    ob[0]   = acc0;
    ob[256] = acc1;
    ob[512] = acc2;
    ob[768] = acc3;
}

// ---------------------------------------------------------------------------
extern "C" void kernel_launch(void* const* d_in, const int* in_sizes, int n_in,
                              void* d_out, int out_size) {
    const float* q    = (const float*)d_in[0];
    const float* k    = (const float*)d_in[1];
    const float* v    = (const float*)d_in[2];
    const float* W    = (const float*)d_in[3];
    const float* bias = (const float*)d_in[4];

    float* out = (float*)d_out;
    const long long out_main = (long long)BATCH * CHW;        // 16777216
    const int write_attn = (out_size >= out_main + BATCH * NAG) ? 1 : 0;
    float* out_attn = out + out_main;

    query_kernel<<<BATCH * 32, 256>>>(q, W, bias);
    score_kernel<<<BATCH, 192>>>(k, out_attn, write_attn);

    const int blocks = (BATCH * V4PB) / (256 * 4);            // 4096
    wsum_kernel<<<blocks, 256>>>(v, out);
}